// round 2
// baseline (speedup 1.0000x reference)
#include <cuda_runtime.h>
#include <cstdint>
#include <cstddef>

// Problem constants
#define TT 4096          // B*S tokens
#define DD 1024          // model dim
#define EE 8             // experts
#define II 1408          // intermediate dim

// GEMM tiling
#define BM 128
#define BN 64
#define BK 32
#define SST 36           // smem row stride (BK + 4 pad): conflict-free frag loads

// ---------------- scratch (__device__ globals; no allocation allowed) ----------------
__device__ int   g_cnt[EE];
__device__ int   g_tok[EE * TT];
__device__ float g_prob[EE * TT];
__device__ float g_h[(size_t)EE * TT * II];   // SwiGLU activations per (expert, slot)

// ---------------- helpers ----------------
__device__ __forceinline__ uint32_t to_tf32(float x) {
    uint32_t r;
    asm("cvt.rna.tf32.f32 %0, %1;" : "=r"(r) : "f"(x));
    return r;
}

__device__ __forceinline__ void mma8(float c[4], const uint32_t a[4], const uint32_t b[2]) {
    asm volatile(
        "mma.sync.aligned.m16n8k8.row.col.f32.tf32.tf32.f32 "
        "{%0,%1,%2,%3},{%4,%5,%6,%7},{%8,%9},{%0,%1,%2,%3};\n"
        : "+f"(c[0]), "+f"(c[1]), "+f"(c[2]), "+f"(c[3])
        : "r"(a[0]), "r"(a[1]), "r"(a[2]), "r"(a[3]), "r"(b[0]), "r"(b[1]));
}

// ---------------- kernel 0: zero output + counters ----------------
__global__ void k_zero(float* __restrict__ out) {
    int idx = blockIdx.x * blockDim.x + threadIdx.x;
    int n = TT * DD;
    for (int i = idx; i < n; i += gridDim.x * blockDim.x) out[i] = 0.f;
    if (idx < EE) g_cnt[idx] = 0;
}

// ---------------- kernel 1: router (fp32 exact) + top2 + softmax + assignment ----------------
__global__ void __launch_bounds__(256) k_router(const float* __restrict__ x,
                                                const float* __restrict__ gate_w) {
    int t = blockIdx.x;
    int warp = threadIdx.x >> 5, lane = threadIdx.x & 31;
    const float* xr = x + (size_t)t * DD;
    const float* wr = gate_w + (size_t)warp * DD;
    float s = 0.f;
    #pragma unroll 8
    for (int k = lane; k < DD; k += 32) s += xr[k] * wr[k];
    #pragma unroll
    for (int o = 16; o; o >>= 1) s += __shfl_xor_sync(0xffffffffu, s, o);

    __shared__ float sc[EE];
    if (lane == 0) sc[warp] = s;
    __syncthreads();

    if (threadIdx.x == 0) {
        // top-1 (lowest index wins ties, matching lax.top_k)
        int i0 = 0; float s0 = sc[0];
        #pragma unroll
        for (int e = 1; e < EE; e++) if (sc[e] > s0) { s0 = sc[e]; i0 = e; }
        // top-2
        int i1 = -1; float s1 = -3.0e38f;
        #pragma unroll
        for (int e = 0; e < EE; e++) if (e != i0 && sc[e] > s1) { s1 = sc[e]; i1 = e; }
        float e1 = expf(s1 - s0);
        float inv = 1.f / (1.f + e1);
        float p0 = inv, p1 = e1 * inv;

        int sl0 = atomicAdd(&g_cnt[i0], 1);
        g_tok[i0 * TT + sl0] = t; g_prob[i0 * TT + sl0] = p0;
        int sl1 = atomicAdd(&g_cnt[i1], 1);
        g_tok[i1 * TT + sl1] = t; g_prob[i1 * TT + sl1] = p1;
    }
}

// ---------------- kernel 2: grouped GEMM1, fused gate+up + SiLU ----------------
// C_g = X_g @ Wg^T ; C_u = X_g @ Wu^T ; h = silu(g)*u  (tf32 mma, fp32 accum)
// Register-prefetch double buffering: tile k+1 global loads issue before the
// mma loop over tile k, hiding DRAM/L2 latency behind tensor work.
__global__ void __launch_bounds__(256) k_gemm1(const float* __restrict__ x,
                                               const float* __restrict__ gproj,
                                               const float* __restrict__ uproj) {
    int e = blockIdx.z;
    int cnt = g_cnt[e];
    int m0 = blockIdx.y * BM;
    if (m0 >= cnt) return;
    int n0 = blockIdx.x * BN;

    __shared__ uint32_t As[BM * SST];
    __shared__ uint32_t Bg[BN * SST];
    __shared__ uint32_t Bu[BN * SST];

    int tid  = threadIdx.x;
    int warp = tid >> 5, lane = tid & 31;
    int wm = (warp >> 1) * 32;      // 4 warps along M
    int wn = (warp & 1) * 32;       // 2 warps along N
    int grp = lane >> 2, tig = lane & 3;

    int arow = tid >> 3;            // 0..31
    int acol = (tid & 7) * 4;       // float4 column

    const float* aptr[4];
    #pragma unroll
    for (int it = 0; it < 4; it++) {
        int slot = m0 + arow + it * 32;
        aptr[it] = (slot < cnt) ? (x + (size_t)g_tok[e * TT + slot] * DD + acol) : nullptr;
    }
    const float* gptr = gproj + ((size_t)e * II + n0 + arow) * DD + acol;
    const float* uptr = uproj + ((size_t)e * II + n0 + arow) * DD + acol;

    float cg[2][4][4], cu[2][4][4];
    #pragma unroll
    for (int mm = 0; mm < 2; mm++)
        #pragma unroll
        for (int nn = 0; nn < 4; nn++)
            #pragma unroll
            for (int q = 0; q < 4; q++) { cg[mm][nn][q] = 0.f; cu[mm][nn][q] = 0.f; }

    float4 va[4], vg[2], vu[2];

    // prefetch tile 0
    #pragma unroll
    for (int it = 0; it < 4; it++)
        va[it] = aptr[it] ? *(const float4*)(aptr[it]) : make_float4(0.f, 0.f, 0.f, 0.f);
    #pragma unroll
    for (int it = 0; it < 2; it++) {
        vg[it] = *(const float4*)(gptr + (size_t)it * 32 * DD);
        vu[it] = *(const float4*)(uptr + (size_t)it * 32 * DD);
    }

    for (int k0 = 0; k0 < DD; k0 += BK) {
        // store current tile to smem (with round-to-nearest tf32 conversion)
        #pragma unroll
        for (int it = 0; it < 4; it++) {
            uint32_t* s = &As[(arow + it * 32) * SST + acol];
            s[0] = to_tf32(va[it].x); s[1] = to_tf32(va[it].y);
            s[2] = to_tf32(va[it].z); s[3] = to_tf32(va[it].w);
        }
        #pragma unroll
        for (int it = 0; it < 2; it++) {
            uint32_t* s = &Bg[(arow + it * 32) * SST + acol];
            s[0] = to_tf32(vg[it].x); s[1] = to_tf32(vg[it].y);
            s[2] = to_tf32(vg[it].z); s[3] = to_tf32(vg[it].w);
            uint32_t* su = &Bu[(arow + it * 32) * SST + acol];
            su[0] = to_tf32(vu[it].x); su[1] = to_tf32(vu[it].y);
            su[2] = to_tf32(vu[it].z); su[3] = to_tf32(vu[it].w);
        }
        __syncthreads();

        // prefetch next tile into registers (overlaps with mma below)
        int kn = k0 + BK;
        if (kn < DD) {
            #pragma unroll
            for (int it = 0; it < 4; it++)
                va[it] = aptr[it] ? *(const float4*)(aptr[it] + kn) : make_float4(0.f, 0.f, 0.f, 0.f);
            #pragma unroll
            for (int it = 0; it < 2; it++) {
                vg[it] = *(const float4*)(gptr + (size_t)it * 32 * DD + kn);
                vu[it] = *(const float4*)(uptr + (size_t)it * 32 * DD + kn);
            }
        }

        #pragma unroll
        for (int ks = 0; ks < 4; ks++) {
            int kk = ks * 8;
            uint32_t a[2][4];
            #pragma unroll
            for (int mm = 0; mm < 2; mm++) {
                int r = wm + mm * 16 + grp;
                a[mm][0] = As[r * SST + kk + tig];
                a[mm][1] = As[(r + 8) * SST + kk + tig];
                a[mm][2] = As[r * SST + kk + tig + 4];
                a[mm][3] = As[(r + 8) * SST + kk + tig + 4];
            }
            #pragma unroll
            for (int nn = 0; nn < 4; nn++) {
                int c = wn + nn * 8 + grp;
                uint32_t bg[2] = { Bg[c * SST + kk + tig], Bg[c * SST + kk + tig + 4] };
                uint32_t bu[2] = { Bu[c * SST + kk + tig], Bu[c * SST + kk + tig + 4] };
                #pragma unroll
                for (int mm = 0; mm < 2; mm++) {
                    mma8(cg[mm][nn], a[mm], bg);
                    mma8(cu[mm][nn], a[mm], bu);
                }
            }
        }
        __syncthreads();
    }

    // epilogue: h = silu(g) * u
    #pragma unroll
    for (int mm = 0; mm < 2; mm++) {
        #pragma unroll
        for (int nn = 0; nn < 4; nn++) {
            int rbase = m0 + wm + mm * 16 + grp;
            int cbase = n0 + wn + nn * 8 + 2 * tig;
            #pragma unroll
            for (int q = 0; q < 4; q++) {
                int slot = rbase + ((q >= 2) ? 8 : 0);
                int c = cbase + (q & 1);
                if (slot < cnt) {
                    float g = cg[mm][nn][q], u = cu[mm][nn][q];
                    float h = (g / (1.f + expf(-g))) * u;
                    g_h[((size_t)e * TT + slot) * II + c] = h;
                }
            }
        }
    }
}

// ---------------- kernel 3: grouped GEMM2 down-proj + prob-scaled scatter ----------------
__global__ void __launch_bounds__(256) k_gemm2(const float* __restrict__ dproj,
                                               float* __restrict__ out) {
    int e = blockIdx.z;
    int cnt = g_cnt[e];
    int m0 = blockIdx.y * BM;
    if (m0 >= cnt) return;
    int n0 = blockIdx.x * BN;

    __shared__ uint32_t As[BM * SST];
    __shared__ uint32_t Bs[BN * SST];

    int tid  = threadIdx.x;
    int warp = tid >> 5, lane = tid & 31;
    int wm = (warp >> 1) * 32;
    int wn = (warp & 1) * 32;
    int grp = lane >> 2, tig = lane & 3;

    int arow = tid >> 3;
    int acol = (tid & 7) * 4;

    const float* aptr[4];
    #pragma unroll
    for (int it = 0; it < 4; it++) {
        int slot = m0 + arow + it * 32;
        aptr[it] = (slot < cnt) ? (g_h + ((size_t)e * TT + slot) * II + acol) : nullptr;
    }
    const float* bptr = dproj + ((size_t)e * DD + n0 + arow) * II + acol;

    float cc[2][4][4];
    #pragma unroll
    for (int mm = 0; mm < 2; mm++)
        #pragma unroll
        for (int nn = 0; nn < 4; nn++)
            #pragma unroll
            for (int q = 0; q < 4; q++) cc[mm][nn][q] = 0.f;

    float4 va[4], vb[2];

    // prefetch tile 0
    #pragma unroll
    for (int it = 0; it < 4; it++)
        va[it] = aptr[it] ? *(const float4*)(aptr[it]) : make_float4(0.f, 0.f, 0.f, 0.f);
    #pragma unroll
    for (int it = 0; it < 2; it++)
        vb[it] = *(const float4*)(bptr + (size_t)it * 32 * II);

    for (int k0 = 0; k0 < II; k0 += BK) {
        #pragma unroll
        for (int it = 0; it < 4; it++) {
            uint32_t* s = &As[(arow + it * 32) * SST + acol];
            s[0] = to_tf32(va[it].x); s[1] = to_tf32(va[it].y);
            s[2] = to_tf32(va[it].z); s[3] = to_tf32(va[it].w);
        }
        #pragma unroll
        for (int it = 0; it < 2; it++) {
            uint32_t* s = &Bs[(arow + it * 32) * SST + acol];
            s[0] = to_tf32(vb[it].x); s[1] = to_tf32(vb[it].y);
            s[2] = to_tf32(vb[it].z); s[3] = to_tf32(vb[it].w);
        }
        __syncthreads();

        int kn = k0 + BK;
        if (kn < II) {
            #pragma unroll
            for (int it = 0; it < 4; it++)
                va[it] = aptr[it] ? *(const float4*)(aptr[it] + kn) : make_float4(0.f, 0.f, 0.f, 0.f);
            #pragma unroll
            for (int it = 0; it < 2; it++)
                vb[it] = *(const float4*)(bptr + (size_t)it * 32 * II + kn);
        }

        #pragma unroll
        for (int ks = 0; ks < 4; ks++) {
            int kk = ks * 8;
            uint32_t a[2][4];
            #pragma unroll
            for (int mm = 0; mm < 2; mm++) {
                int r = wm + mm * 16 + grp;
                a[mm][0] = As[r * SST + kk + tig];
                a[mm][1] = As[(r + 8) * SST + kk + tig];
                a[mm][2] = As[r * SST + kk + tig + 4];
                a[mm][3] = As[(r + 8) * SST + kk + tig + 4];
            }
            #pragma unroll
            for (int nn = 0; nn < 4; nn++) {
                int c = wn + nn * 8 + grp;
                uint32_t b[2] = { Bs[c * SST + kk + tig], Bs[c * SST + kk + tig + 4] };
                #pragma unroll
                for (int mm = 0; mm < 2; mm++) mma8(cc[mm][nn], a[mm], b);
            }
        }
        __syncthreads();
    }

    // epilogue: out[token, d] += prob * val  (cross-expert races via atomicAdd/REDG)
    #pragma unroll
    for (int mm = 0; mm < 2; mm++) {
        int rb = m0 + wm + mm * 16 + grp;
        #pragma unroll
        for (int rh = 0; rh < 2; rh++) {
            int slot = rb + rh * 8;
            if (slot < cnt) {
                int   t = g_tok[e * TT + slot];
                float p = g_prob[e * TT + slot];
                float* orow = out + (size_t)t * DD;
                #pragma unroll
                for (int nn = 0; nn < 4; nn++) {
                    int c = n0 + wn + nn * 8 + 2 * tig;
                    atomicAdd(&orow[c],     p * cc[mm][nn][rh * 2 + 0]);
                    atomicAdd(&orow[c + 1], p * cc[mm][nn][rh * 2 + 1]);
                }
            }
        }
    }
}

// ---------------- launch ----------------
extern "C" void kernel_launch(void* const* d_in, const int* in_sizes, int n_in,
                              void* d_out, int out_size) {
    const float* x      = (const float*)d_in[0];
    const float* gate_w = (const float*)d_in[1];
    const float* gproj  = (const float*)d_in[2];
    const float* uproj  = (const float*)d_in[3];
    const float* dproj  = (const float*)d_in[4];
    float* out = (float*)d_out;

    k_zero<<<1024, 256>>>(out);
    k_router<<<TT, 256>>>(x, gate_w);
    k_gemm1<<<dim3(II / BN, TT / BM, EE), 256>>>(x, gproj, uproj);
    k_gemm2<<<dim3(DD / BN, TT / BM, EE), 256>>>(dproj, out);
}

// round 17
// speedup vs baseline: 1.0113x; 1.0113x over previous
#include <cuda_runtime.h>
#include <cstdint>
#include <cstddef>

// Problem constants
#define TT 4096          // B*S tokens
#define DD 1024          // model dim
#define EE 8             // experts
#define II 1408          // intermediate dim

// GEMM tiling
#define BM 128
#define BK 32
#define SST 36           // padded smem row stride (words): conflict-free frags

// ---------------- scratch (__device__ globals; no allocation allowed) ----------------
__device__ int   g_cnt[EE];
__device__ int   g_tok[EE * TT];
__device__ float g_prob[EE * TT];
__device__ float g_h[(size_t)EE * TT * II];   // SwiGLU activations per (expert, slot)

// ---------------- helpers ----------------
__device__ __forceinline__ uint32_t to_tf32(float x) {
    uint32_t r;
    asm("cvt.rna.tf32.f32 %0, %1;" : "=r"(r) : "f"(x));
    return r;
}
__device__ __forceinline__ void mma8(float c[4], const uint32_t a[4], const uint32_t b[2]) {
    asm volatile(
        "mma.sync.aligned.m16n8k8.row.col.f32.tf32.tf32.f32 "
        "{%0,%1,%2,%3},{%4,%5,%6,%7},{%8,%9},{%0,%1,%2,%3};\n"
        : "+f"(c[0]), "+f"(c[1]), "+f"(c[2]), "+f"(c[3])
        : "r"(a[0]), "r"(a[1]), "r"(a[2]), "r"(a[3]), "r"(b[0]), "r"(b[1]));
}
__device__ __forceinline__ void st4(uint32_t* p, float4 v) {
    *(uint4*)p = make_uint4(to_tf32(v.x), to_tf32(v.y), to_tf32(v.z), to_tf32(v.w));
}

// word-offsets in dynamic smem
#define AW (BM * SST)            // 4608 words (A tile)
// gemm1: stage = A + Bg(64) + Bu(64); gemm2: stage = A + B(128) -> both 9216 words
#define STG1 (AW + 2 * (64 * SST))
#define STG2 (AW + 128 * SST)
#define SMEM_BYTES (2 * 9216 * 4)  // 73728 both kernels

// ---------------- kernel 0: zero output + counters ----------------
__global__ void k_zero(float* __restrict__ out) {
    int idx = blockIdx.x * blockDim.x + threadIdx.x;
    int n = TT * DD;
    for (int i = idx; i < n; i += gridDim.x * blockDim.x) out[i] = 0.f;
    if (idx < EE) g_cnt[idx] = 0;
}

// ---------------- kernel 1: router (fp32 exact) + top2 + softmax + assignment ----------------
__global__ void __launch_bounds__(256) k_router(const float* __restrict__ x,
                                                const float* __restrict__ gate_w) {
    int t = blockIdx.x;
    int warp = threadIdx.x >> 5, lane = threadIdx.x & 31;
    const float* xr = x + (size_t)t * DD;
    const float* wr = gate_w + (size_t)warp * DD;
    float s = 0.f;
    #pragma unroll 8
    for (int k = lane; k < DD; k += 32) s += xr[k] * wr[k];
    #pragma unroll
    for (int o = 16; o; o >>= 1) s += __shfl_xor_sync(0xffffffffu, s, o);

    __shared__ float sc[EE];
    if (lane == 0) sc[warp] = s;
    __syncthreads();

    if (threadIdx.x == 0) {
        int i0 = 0; float s0 = sc[0];
        #pragma unroll
        for (int e = 1; e < EE; e++) if (sc[e] > s0) { s0 = sc[e]; i0 = e; }
        int i1 = -1; float s1 = -3.0e38f;
        #pragma unroll
        for (int e = 0; e < EE; e++) if (e != i0 && sc[e] > s1) { s1 = sc[e]; i1 = e; }
        float e1 = expf(s1 - s0);
        float inv = 1.f / (1.f + e1);
        float p0 = inv, p1 = e1 * inv;

        int sl0 = atomicAdd(&g_cnt[i0], 1);
        g_tok[i0 * TT + sl0] = t; g_prob[i0 * TT + sl0] = p0;
        int sl1 = atomicAdd(&g_cnt[i1], 1);
        g_tok[i1 * TT + sl1] = t; g_prob[i1 * TT + sl1] = p1;
    }
}

// ---------------- kernel 2: grouped GEMM1 (gate+up fused) + SiLU ----------------
// Tile 128 x (64|64) x 32. 8 warps (4x2), warp tile 32x32 per matrix.
// 2-stage smem pipeline, one __syncthreads per k-tile, register LDG prefetch.
__global__ void __launch_bounds__(256) k_gemm1(const float* __restrict__ x,
                                               const float* __restrict__ gproj,
                                               const float* __restrict__ uproj) {
    extern __shared__ uint32_t smu[];
    int e = blockIdx.z;
    int cnt = g_cnt[e];
    int m0 = blockIdx.y * BM;
    if (m0 >= cnt) return;
    int n0 = blockIdx.x * 64;

    int tid  = threadIdx.x;
    int warp = tid >> 5, lane = tid & 31;
    int wm = (warp >> 1) * 32;
    int wn = (warp & 1) * 32;
    int grp = lane >> 2, tig = lane & 3;

    // loader geometry: 256 threads, rows (tid>>3)+32i, float4 col tid&7
    int lrow = tid >> 3, lf4 = (tid & 7) * 4;
    uint32_t so0 = lrow * SST + lf4;             // word offset; +i*32*SST per chunk

    const float* ap[4];
    #pragma unroll
    for (int i = 0; i < 4; i++) {
        int slot = m0 + lrow + 32 * i;
        ap[i] = (slot < cnt) ? x + (size_t)g_tok[e * TT + slot] * DD + lf4 : nullptr;
    }
    const float* gp = gproj + ((size_t)e * II + n0 + lrow) * DD + lf4;
    const float* up = uproj + ((size_t)e * II + n0 + lrow) * DD + lf4;

    float cg[2][4][4], cu[2][4][4];
    #pragma unroll
    for (int mm = 0; mm < 2; mm++)
        #pragma unroll
        for (int nn = 0; nn < 4; nn++)
            #pragma unroll
            for (int q = 0; q < 4; q++) { cg[mm][nn][q] = 0.f; cu[mm][nn][q] = 0.f; }

    float4 va[4], vg[2], vu[2];
    #pragma unroll
    for (int i = 0; i < 4; i++)
        va[i] = ap[i] ? *(const float4*)(ap[i]) : make_float4(0.f, 0.f, 0.f, 0.f);
    #pragma unroll
    for (int j = 0; j < 2; j++) {
        vg[j] = *(const float4*)(gp + (size_t)j * 32 * DD);
        vu[j] = *(const float4*)(up + (size_t)j * 32 * DD);
    }

    const int KT = DD / BK;  // 32
    for (int kt = 0; kt < KT; kt++) {
        uint32_t* As = smu + (kt & 1) * STG1;
        uint32_t* Bg = As + AW;
        uint32_t* Bu = Bg + 64 * SST;
        #pragma unroll
        for (int i = 0; i < 4; i++) st4(As + so0 + i * 32 * SST, va[i]);
        #pragma unroll
        for (int j = 0; j < 2; j++) {
            st4(Bg + so0 + j * 32 * SST, vg[j]);
            st4(Bu + so0 + j * 32 * SST, vu[j]);
        }
        __syncthreads();

        if (kt + 1 < KT) {
            int k0 = (kt + 1) * BK;
            #pragma unroll
            for (int i = 0; i < 4; i++)
                va[i] = ap[i] ? *(const float4*)(ap[i] + k0) : make_float4(0.f, 0.f, 0.f, 0.f);
            #pragma unroll
            for (int j = 0; j < 2; j++) {
                vg[j] = *(const float4*)(gp + (size_t)j * 32 * DD + k0);
                vu[j] = *(const float4*)(up + (size_t)j * 32 * DD + k0);
            }
        }

        #pragma unroll
        for (int ks = 0; ks < 4; ks++) {
            int kk = ks * 8;
            uint32_t a[2][4];
            #pragma unroll
            for (int mm = 0; mm < 2; mm++) {
                int r = wm + mm * 16 + grp;
                const uint32_t* pa = As + r * SST + kk + tig;
                a[mm][0] = pa[0]; a[mm][1] = pa[8 * SST]; a[mm][2] = pa[4]; a[mm][3] = pa[8 * SST + 4];
            }
            #pragma unroll
            for (int nn = 0; nn < 4; nn++) {
                int c = wn + nn * 8 + grp;
                const uint32_t* pg = Bg + c * SST + kk + tig;
                const uint32_t* pu = Bu + c * SST + kk + tig;
                uint32_t bg[2] = { pg[0], pg[4] };
                uint32_t bu[2] = { pu[0], pu[4] };
                #pragma unroll
                for (int mm = 0; mm < 2; mm++) {
                    mma8(cg[mm][nn], a[mm], bg);
                    mma8(cu[mm][nn], a[mm], bu);
                }
            }
        }
        // next iteration's stores go to the other stage; the next sync orders reuse
    }

    // epilogue: h = silu(g) * u
    #pragma unroll
    for (int mm = 0; mm < 2; mm++) {
        #pragma unroll
        for (int rh = 0; rh < 2; rh++) {
            int slot = m0 + wm + mm * 16 + grp + rh * 8;
            if (slot < cnt) {
                float* dst = g_h + ((size_t)e * TT + slot) * II + n0;
                #pragma unroll
                for (int nn = 0; nn < 4; nn++) {
                    int c = wn + nn * 8 + 2 * tig;
                    float g0 = cg[mm][nn][rh * 2 + 0], u0 = cu[mm][nn][rh * 2 + 0];
                    float g1 = cg[mm][nn][rh * 2 + 1], u1 = cu[mm][nn][rh * 2 + 1];
                    dst[c]     = g0 / (1.f + expf(-g0)) * u0;
                    dst[c + 1] = g1 / (1.f + expf(-g1)) * u1;
                }
            }
        }
    }
}

// ---------------- kernel 3: grouped GEMM2 down-proj + prob-scaled scatter ----------------
// Tile 128 x 128 x 32. 8 warps (4x2), warp tile 32x64. Same pipeline.
__global__ void __launch_bounds__(256) k_gemm2(const float* __restrict__ dproj,
                                               float* __restrict__ out) {
    extern __shared__ uint32_t smu[];
    int e = blockIdx.z;
    int cnt = g_cnt[e];
    int m0 = blockIdx.y * BM;
    if (m0 >= cnt) return;
    int n0 = blockIdx.x * 128;

    int tid  = threadIdx.x;
    int warp = tid >> 5, lane = tid & 31;
    int wm = (warp >> 1) * 32;
    int wn = (warp & 1) * 64;
    int grp = lane >> 2, tig = lane & 3;

    int lrow = tid >> 3, lf4 = (tid & 7) * 4;
    uint32_t so0 = lrow * SST + lf4;

    const float* ap[4];
    #pragma unroll
    for (int i = 0; i < 4; i++) {
        int slot = m0 + lrow + 32 * i;
        ap[i] = (slot < cnt) ? g_h + ((size_t)e * TT + slot) * II + lf4 : nullptr;
    }
    const float* bp = dproj + ((size_t)e * DD + n0 + lrow) * II + lf4;

    float cc[2][8][4];
    #pragma unroll
    for (int mm = 0; mm < 2; mm++)
        #pragma unroll
        for (int nn = 0; nn < 8; nn++)
            #pragma unroll
            for (int q = 0; q < 4; q++) cc[mm][nn][q] = 0.f;

    float4 va[4], vb[4];
    #pragma unroll
    for (int i = 0; i < 4; i++) {
        va[i] = ap[i] ? *(const float4*)(ap[i]) : make_float4(0.f, 0.f, 0.f, 0.f);
        vb[i] = *(const float4*)(bp + (size_t)i * 32 * II);
    }

    const int KT = II / BK;  // 44
    for (int kt = 0; kt < KT; kt++) {
        uint32_t* As = smu + (kt & 1) * STG2;
        uint32_t* Bs = As + AW;
        #pragma unroll
        for (int i = 0; i < 4; i++) {
            st4(As + so0 + i * 32 * SST, va[i]);
            st4(Bs + so0 + i * 32 * SST, vb[i]);
        }
        __syncthreads();

        if (kt + 1 < KT) {
            int k0 = (kt + 1) * BK;
            #pragma unroll
            for (int i = 0; i < 4; i++) {
                va[i] = ap[i] ? *(const float4*)(ap[i] + k0) : make_float4(0.f, 0.f, 0.f, 0.f);
                vb[i] = *(const float4*)(bp + (size_t)i * 32 * II + k0);
            }
        }

        #pragma unroll
        for (int ks = 0; ks < 4; ks++) {
            int kk = ks * 8;
            uint32_t a[2][4];
            #pragma unroll
            for (int mm = 0; mm < 2; mm++) {
                int r = wm + mm * 16 + grp;
                const uint32_t* pa = As + r * SST + kk + tig;
                a[mm][0] = pa[0]; a[mm][1] = pa[8 * SST]; a[mm][2] = pa[4]; a[mm][3] = pa[8 * SST + 4];
            }
            #pragma unroll
            for (int nn = 0; nn < 8; nn++) {
                int c = wn + nn * 8 + grp;
                const uint32_t* pb = Bs + c * SST + kk + tig;
                uint32_t b[2] = { pb[0], pb[4] };
                #pragma unroll
                for (int mm = 0; mm < 2; mm++) mma8(cc[mm][nn], a[mm], b);
            }
        }
    }

    // epilogue: out[token] += prob * val (cross-expert races -> atomicAdd/REDG)
    #pragma unroll
    for (int mm = 0; mm < 2; mm++) {
        #pragma unroll
        for (int rh = 0; rh < 2; rh++) {
            int slot = m0 + wm + mm * 16 + grp + rh * 8;
            if (slot < cnt) {
                int   t = g_tok[e * TT + slot];
                float p = g_prob[e * TT + slot];
                float* dst = out + (size_t)t * DD + n0;
                #pragma unroll
                for (int nn = 0; nn < 8; nn++) {
                    int c = wn + nn * 8 + 2 * tig;
                    atomicAdd(&dst[c],     p * cc[mm][nn][rh * 2 + 0]);
                    atomicAdd(&dst[c + 1], p * cc[mm][nn][rh * 2 + 1]);
                }
            }
        }
    }
}

// ---------------- launch ----------------
extern "C" void kernel_launch(void* const* d_in, const int* in_sizes, int n_in,
                              void* d_out, int out_size) {
    const float* x      = (const float*)d_in[0];
    const float* gate_w = (const float*)d_in[1];
    const float* gproj  = (const float*)d_in[2];
    const float* uproj  = (const float*)d_in[3];
    const float* dproj  = (const float*)d_in[4];
    float* out = (float*)d_out;

    cudaFuncSetAttribute(k_gemm1, cudaFuncAttributeMaxDynamicSharedMemorySize, SMEM_BYTES);
    cudaFuncSetAttribute(k_gemm2, cudaFuncAttributeMaxDynamicSharedMemorySize, SMEM_BYTES);

    k_zero<<<1024, 256>>>(out);
    k_router<<<TT, 256>>>(x, gate_w);
    k_gemm1<<<dim3(II / 64, TT / BM, EE), 256, SMEM_BYTES>>>(x, gproj, uproj);
    k_gemm2<<<dim3(DD / 128, TT / BM, EE), 256, SMEM_BYTES>>>(dproj, out);
}